// round 4
// baseline (speedup 1.0000x reference)
#include <cuda_runtime.h>

// SplitWin_Normalize R4: 2 kernels.
//  K1: stage 1 (w=41, gap=20, clip=3): streaming interior tiles with a
//      per-thread smem ring (each src row fetched from DRAM once), plus
//      brute-force edge-bin blocks folded into the same grid.
//  K2: stages 2+3 fused: produces c2 (clip=2) into a 32-slot smem ring
//      (never touches DRAM), box25-filters it incrementally, and writes
//      out = x / filtered. Edge c2 bins brute-forced inline.
// Layout: (4096 bins [stride NL], 4096 lines [contiguous]).

static const int NB = 4096;
static const int NL = 4096;
static const int TB = 256;        // bins per stream tile
static const int NT = 64;         // threads per block (= lines per block)
static const int NTILES = NB / TB;

__device__ float g_c1[NB * NL];   // stage-1 result

__device__ __forceinline__ int refl(int p)
{
    if (p < 0)   return -1 - p;
    if (p >= NB) return 2 * NB - 1 - p;
    return p;
}

// brute-force smoothed + clip for one bin (used for edge bins)
__device__ __forceinline__ float brute_clip(const float* __restrict__ src,
                                            int i, int l, float clip)
{
    const float SC = 0.5f / 41.0f;
    int f = (i + 41 < NB) ? (i + 41) : (2 * NB - 43 - i);
    int a = (i <= 41) ? (41 - i) : (i - 42);
    float sf = 0.0f, sa = 0.0f;
    #pragma unroll 4
    for (int k = -20; k <= 20; ++k) {
        sf += src[refl(f + k) * NL + l];
        sa += src[refl(a + k) * NL + l];
    }
    float sm = (sf + sa) * SC;
    float xv = src[i * NL + l];
    return (xv > clip * sm) ? sm : xv;
}

// ---------------------------------------------------------------------------
// K1: stage 1. grid = (NL/NT, NTILES + 83). y >= NTILES rows are edge bins.
// ---------------------------------------------------------------------------
__global__ void k1_stage1(const float* __restrict__ x)
{
    __shared__ float ring[128 * NT];
    const int tid = threadIdx.x;
    const int l   = blockIdx.x * NT + tid;
    const float SC = 0.5f / 41.0f;

    if (blockIdx.y >= NTILES) {
        int j = blockIdx.y - NTILES;                 // 0..82
        int i = (j < 42) ? j : (NB - 41 + (j - 42));
        g_c1[i * NL + l] = brute_clip(x, i, l, 3.0f);
        return;
    }

    const int t0 = blockIdx.y * TB;
    int i0 = (t0 < 42) ? 42 : t0;
    int i1 = t0 + TB - 1;
    if (i1 > NB - 42) i1 = NB - 42;

    // preload virtual rows [i0-62, i0+61]; init windows
    float Wf = 0.0f, Wa = 0.0f;
    #pragma unroll 4
    for (int v = i0 - 62; v <= i0 + 61; ++v) {
        float val = x[refl(v) * NL + l];
        ring[(v & 127) * NT + tid] = val;
        if (v >= i0 + 21) Wf += val;   // filtered[i0+41] window
        if (v <= i0 - 22) Wa += val;   // filtered[i0-42] window
    }

    #pragma unroll 8
    for (int i = i0;;) {
        float sm = (Wf + Wa) * SC;
        float xv = ring[(i & 127) * NT + tid];
        g_c1[i * NL + l] = (xv > 3.0f * sm) ? sm : xv;
        if (++i > i1) break;
        float nv = x[refl(i + 61) * NL + l];
        ring[((i + 61) & 127) * NT + tid] = nv;
        Wf += nv - ring[((i + 20) & 127) * NT + tid];
        Wa += ring[((i - 22) & 127) * NT + tid]
            - ring[((i - 63) & 127) * NT + tid];
    }
}

// ---------------------------------------------------------------------------
// K2: stage 2 (clip=2) fused with stage 3 (box25) and final divide.
// grid = (NL/NT, NTILES). c2 lives only in a 32-slot smem ring.
// ---------------------------------------------------------------------------
__global__ void k2_stage23(const float* __restrict__ x,
                           float* __restrict__ out)
{
    __shared__ float r1[128 * NT];   // c1 source ring (virtual row & 127)
    __shared__ float r2[32 * NT];    // c2 ring (bin & 31)
    const int tid = threadIdx.x;
    const int l   = blockIdx.x * NT + tid;
    const int t0  = blockIdx.y * TB;
    const float SC  = 0.5f / 41.0f;
    const float R25 = 1.0f / 25.0f;
    const float* __restrict__ c1 = g_c1;

    bool winit = false;
    float Wf = 0.0f, Wa = 0.0f;

    auto produce = [&](int j) {
        float c2v;
        if (j < 42 || j > NB - 42) {
            c2v = brute_clip(c1, j, l, 2.0f);
        } else {
            if (!winit) {
                Wf = 0.0f; Wa = 0.0f;
                #pragma unroll 4
                for (int v = j - 62; v <= j + 61; ++v) {
                    float val = c1[refl(v) * NL + l];
                    r1[(v & 127) * NT + tid] = val;
                    if (v >= j + 21) Wf += val;
                    if (v <= j - 22) Wa += val;
                }
                winit = true;
            } else {
                float nv = c1[refl(j + 61) * NL + l];
                r1[((j + 61) & 127) * NT + tid] = nv;
                Wf += nv - r1[((j + 20) & 127) * NT + tid];
                Wa += r1[((j - 22) & 127) * NT + tid]
                    - r1[((j - 63) & 127) * NT + tid];
            }
            float sm = (Wf + Wa) * SC;
            float cv = r1[(j & 127) * NT + tid];
            c2v = (cv > 2.0f * sm) ? sm : cv;
        }
        r2[(j & 31) * NT + tid] = c2v;
    };

    // warm-up: produce c2 for j in [max(0, t0-12), t0+12]
    int jp0 = (t0 >= 12) ? (t0 - 12) : 0;
    for (int j = jp0; j <= t0 + 12; ++j) produce(j);

    // init box25 window at i = t0
    float W3 = 0.0f;
    #pragma unroll
    for (int k = -12; k <= 12; ++k)
        W3 += r2[(refl(t0 + k) & 31) * NT + tid];

    const int iend = t0 + TB - 1;
    #pragma unroll 1
    for (int i = t0;;) {
        out[i * NL + l] = __fdiv_rn(x[i * NL + l], W3 * R25);
        if (++i > iend) break;
        int jn = i + 12;
        if (jn <= NB - 1) produce(jn);
        W3 += r2[(refl(jn) & 31) * NT + tid]
            - r2[(refl(i - 13) & 31) * NT + tid];
    }
}

// ---------------------------------------------------------------------------
extern "C" void kernel_launch(void* const* d_in, const int* in_sizes, int n_in,
                              void* d_out, int out_size)
{
    const float* x = (const float*)d_in[0];
    float* out     = (float*)d_out;

    dim3 blk(NT);
    dim3 g1(NL / NT, NTILES + 83);   // stream tiles + 83 edge-bin rows
    dim3 g2(NL / NT, NTILES);

    k1_stage1 <<<g1, blk>>>(x);
    k2_stage23<<<g2, blk>>>(x, out);
}

// round 5
// speedup vs baseline: 4.7366x; 4.7366x over previous
#include <cuda_runtime.h>

// SplitWin_Normalize R5: R3 register-streaming skeleton, repaired.
//  - float4 across lines (4 lines per thread), LDG.128/STG.128.
//  - trailing window update + unroll 4 -> batched loads, MLP ~16.
//  - 83 edge bins folded into the stage grids (no serialized edge kernels).
//  - stage 3 (box25 + divide) separate float4 streaming kernel.
// Layout: (4096 bins [stride NL], 4096 lines [contiguous]).

static const int NB = 4096;
static const int NL = 4096;
static const int TB = 64;            // bins per thread in stream tiles
static const int NTY = NB / TB;      // 64 stream tiles
static const int THREADS = 256;
static const int L4N = NL / 4;       // float4s per row

__device__ float g_c1[NB * NL];
__device__ float g_c2[NB * NL];

__device__ __forceinline__ int refl(int p)
{
    if (p < 0)   return -1 - p;
    if (p >= NB) return 2 * NB - 1 - p;
    return p;
}

__device__ __forceinline__ float4 ld4(const float* __restrict__ p, int row, int l4)
{
    return __ldg(reinterpret_cast<const float4*>(p) + row * L4N + l4);
}

__device__ __forceinline__ float4 f4add(float4 a, float4 b)
{ return make_float4(a.x + b.x, a.y + b.y, a.z + b.z, a.w + b.w); }
__device__ __forceinline__ float4 f4sub(float4 a, float4 b)
{ return make_float4(a.x - b.x, a.y - b.y, a.z - b.z, a.w - b.w); }
__device__ __forceinline__ float4 f4scale(float4 a, float s)
{ return make_float4(a.x * s, a.y * s, a.z * s, a.w * s); }
// out = (x > clip*sm) ? sm : x
__device__ __forceinline__ float4 f4clip(float4 xv, float4 sm, float clip)
{
    return make_float4((xv.x > clip * sm.x) ? sm.x : xv.x,
                       (xv.y > clip * sm.y) ? sm.y : xv.y,
                       (xv.z > clip * sm.z) ? sm.z : xv.z,
                       (xv.w > clip * sm.w) ? sm.w : xv.w);
}

// ---------------------------------------------------------------------------
// Stage kernel (w=41, gap=20): grid = (L4N/THREADS, NTY + 83).
//  y <  NTY : streaming interior tile [max(42,y*TB), min(y*TB+TB-1, NB-42)]
//  y >= NTY : one edge bin, brute-forced.
// ---------------------------------------------------------------------------
__global__ void stage_kernel(const float* __restrict__ src,
                             float* __restrict__ dst, float clip)
{
    const int l4 = blockIdx.x * THREADS + threadIdx.x;
    const float SC = 0.5f / 41.0f;
    float4* __restrict__ dst4 = reinterpret_cast<float4*>(dst);

    if (blockIdx.y >= NTY) {
        // edge bin: i in [0,42) or (NB-42, NB-1]
        int j = blockIdx.y - NTY;                    // 0..82
        int i = (j < 42) ? j : (NB - 41 + (j - 42));
        int f = (i + 41 < NB) ? (i + 41) : (2 * NB - 43 - i);
        int a = (i <= 41) ? (41 - i) : (i - 42);
        float4 sf = make_float4(0.f, 0.f, 0.f, 0.f);
        float4 sa = make_float4(0.f, 0.f, 0.f, 0.f);
        #pragma unroll 4
        for (int k = -20; k <= 20; ++k) {
            sf = f4add(sf, ld4(src, refl(f + k), l4));
            sa = f4add(sa, ld4(src, refl(a + k), l4));
        }
        float4 sm = f4scale(f4add(sf, sa), SC);
        float4 xv = ld4(src, i, l4);
        dst4[i * L4N + l4] = f4clip(xv, sm, clip);
        return;
    }

    const int t0 = blockIdx.y * TB;
    int i0 = (t0 < 42) ? 42 : t0;
    int i1 = t0 + TB - 1;
    if (i1 > NB - 42) i1 = NB - 42;

    // init: Wf = sum rows [i0+21, i0+61], Wa = sum rows [i0-62, i0-22]
    float4 Wf = make_float4(0.f, 0.f, 0.f, 0.f);
    float4 Wa = make_float4(0.f, 0.f, 0.f, 0.f);
    #pragma unroll 4
    for (int k = 21; k <= 61; ++k) Wf = f4add(Wf, ld4(src, refl(i0 + k), l4));
    #pragma unroll 4
    for (int k = 22; k <= 62; ++k) Wa = f4add(Wa, ld4(src, refl(i0 - k), l4));

    #pragma unroll 4
    for (int i = i0; i <= i1; ++i) {
        float4 sm = f4scale(f4add(Wf, Wa), SC);
        float4 xv = ld4(src, i, l4);
        dst4[i * L4N + l4] = f4clip(xv, sm, clip);
        // trailing update toward i+1 (extra update at i1 is harmless)
        float4 nf = ld4(src, refl(i + 62), l4);
        float4 of = ld4(src, refl(i + 21), l4);
        float4 na = ld4(src, refl(i - 21), l4);
        float4 oa = ld4(src, refl(i - 62), l4);
        Wf = f4add(Wf, f4sub(nf, of));
        Wa = f4add(Wa, f4sub(na, oa));
    }
}

// ---------------------------------------------------------------------------
// Stage 3 (w=25, gap=0) + final divide: out = x / box25(c2).
// grid = (L4N/THREADS, NTY). Reflect-aware incremental window (exact).
// ---------------------------------------------------------------------------
__global__ void stage3_kernel(const float* __restrict__ c2,
                              const float* __restrict__ x,
                              float* __restrict__ out)
{
    const int l4 = blockIdx.x * THREADS + threadIdx.x;
    const int t0 = blockIdx.y * TB;
    const int i1 = t0 + TB - 1;
    const float R25 = 1.0f / 25.0f;
    float4* __restrict__ out4 = reinterpret_cast<float4*>(out);

    float4 W = make_float4(0.f, 0.f, 0.f, 0.f);
    #pragma unroll
    for (int k = -12; k <= 12; ++k)
        W = f4add(W, ld4(c2, refl(t0 + k), l4));

    #pragma unroll 4
    for (int i = t0; i <= i1; ++i) {
        float4 f  = f4scale(W, R25);
        float4 xv = ld4(x, i, l4);
        out4[i * L4N + l4] = make_float4(__fdiv_rn(xv.x, f.x),
                                         __fdiv_rn(xv.y, f.y),
                                         __fdiv_rn(xv.z, f.z),
                                         __fdiv_rn(xv.w, f.w));
        // trailing update toward i+1
        W = f4add(W, f4sub(ld4(c2, refl(i + 13), l4),
                           ld4(c2, refl(i - 12), l4)));
    }
}

// ---------------------------------------------------------------------------
extern "C" void kernel_launch(void* const* d_in, const int* in_sizes, int n_in,
                              void* d_out, int out_size)
{
    const float* x = (const float*)d_in[0];
    float* out     = (float*)d_out;

    float *c1 = nullptr, *c2 = nullptr;
    cudaGetSymbolAddress((void**)&c1, g_c1);
    cudaGetSymbolAddress((void**)&c2, g_c2);

    dim3 blk(THREADS);
    dim3 gStage(L4N / THREADS, NTY + 83);   // (4, 147): tiles + edge bins
    dim3 gS3(L4N / THREADS, NTY);           // (4, 64)

    stage_kernel<<<gStage, blk>>>(x,  c1, 3.0f);
    stage_kernel<<<gStage, blk>>>(c1, c2, 2.0f);
    stage3_kernel<<<gS3, blk>>>(c2, x, out);
}

// round 6
// speedup vs baseline: 6.1370x; 1.2957x over previous
#include <cuda_runtime.h>

// SplitWin_Normalize R6: R5 skeleton with (1) TB=32 for 2x interior
// parallelism (512 interior blocks ~ 28 warps/SM) and (2) a no-reflect
// fast path for the 124/128 tiles whose full access window is in-bounds
// (inner loop = 5 LDG.128 + FADDs, no refl branches).
// Layout: (4096 bins [stride NL], 4096 lines [contiguous]).

static const int NB = 4096;
static const int NL = 4096;
static const int TB = 32;            // bins per thread in stream tiles
static const int NTY = NB / TB;      // 128 stream tiles
static const int THREADS = 256;
static const int L4N = NL / 4;       // float4s per row

__device__ float g_c1[NB * NL];
__device__ float g_c2[NB * NL];

__device__ __forceinline__ int refl(int p)
{
    if (p < 0)   return -1 - p;
    if (p >= NB) return 2 * NB - 1 - p;
    return p;
}

__device__ __forceinline__ float4 ld4(const float* __restrict__ p, int row, int l4)
{
    return __ldg(reinterpret_cast<const float4*>(p) + row * L4N + l4);
}

__device__ __forceinline__ float4 f4add(float4 a, float4 b)
{ return make_float4(a.x + b.x, a.y + b.y, a.z + b.z, a.w + b.w); }
__device__ __forceinline__ float4 f4sub(float4 a, float4 b)
{ return make_float4(a.x - b.x, a.y - b.y, a.z - b.z, a.w - b.w); }
__device__ __forceinline__ float4 f4scale(float4 a, float s)
{ return make_float4(a.x * s, a.y * s, a.z * s, a.w * s); }
__device__ __forceinline__ float4 f4clip(float4 xv, float4 sm, float clip)
{
    return make_float4((xv.x > clip * sm.x) ? sm.x : xv.x,
                       (xv.y > clip * sm.y) ? sm.y : xv.y,
                       (xv.z > clip * sm.z) ? sm.z : xv.z,
                       (xv.w > clip * sm.w) ? sm.w : xv.w);
}

// ---------------------------------------------------------------------------
// Stage kernel (w=41, gap=20): grid = (L4N/THREADS, NTY + 83).
//  y <  NTY : streaming interior tile (fast path when no reflect possible)
//  y >= NTY : one edge bin, brute-forced.
// ---------------------------------------------------------------------------
__global__ void stage_kernel(const float* __restrict__ src,
                             float* __restrict__ dst, float clip)
{
    const int l4 = blockIdx.x * THREADS + threadIdx.x;
    const float SC = 0.5f / 41.0f;
    float4* __restrict__ dst4 = reinterpret_cast<float4*>(dst);

    if (blockIdx.y >= NTY) {
        int j = blockIdx.y - NTY;                    // 0..82
        int i = (j < 42) ? j : (NB - 41 + (j - 42));
        int f = (i + 41 < NB) ? (i + 41) : (2 * NB - 43 - i);
        int a = (i <= 41) ? (41 - i) : (i - 42);
        float4 sf = make_float4(0.f, 0.f, 0.f, 0.f);
        float4 sa = make_float4(0.f, 0.f, 0.f, 0.f);
        #pragma unroll 4
        for (int k = -20; k <= 20; ++k) {
            sf = f4add(sf, ld4(src, refl(f + k), l4));
            sa = f4add(sa, ld4(src, refl(a + k), l4));
        }
        float4 sm = f4scale(f4add(sf, sa), SC);
        float4 xv = ld4(src, i, l4);
        dst4[i * L4N + l4] = f4clip(xv, sm, clip);
        return;
    }

    const int t0 = blockIdx.y * TB;
    int i0 = (t0 < 42) ? 42 : t0;
    int i1 = t0 + TB - 1;
    if (i1 > NB - 42) i1 = NB - 42;
    if (i0 > i1) return;                             // empty clamped tiles

    float4 Wf = make_float4(0.f, 0.f, 0.f, 0.f);
    float4 Wa = make_float4(0.f, 0.f, 0.f, 0.f);

    const bool fast = (t0 >= 62) && (t0 + TB - 1 + 62 <= NB - 1);

    if (fast) {
        // init windows, no reflection anywhere in this tile
        #pragma unroll 4
        for (int k = 21; k <= 61; ++k) Wf = f4add(Wf, ld4(src, i0 + k, l4));
        #pragma unroll 4
        for (int k = 22; k <= 62; ++k) Wa = f4add(Wa, ld4(src, i0 - k, l4));

        #pragma unroll 8
        for (int i = i0; i <= i1; ++i) {
            float4 sm = f4scale(f4add(Wf, Wa), SC);
            float4 xv = ld4(src, i, l4);
            dst4[i * L4N + l4] = f4clip(xv, sm, clip);
            float4 nf = ld4(src, i + 62, l4);
            float4 of = ld4(src, i + 21, l4);
            float4 na = ld4(src, i - 21, l4);
            float4 oa = ld4(src, i - 62, l4);
            Wf = f4add(Wf, f4sub(nf, of));
            Wa = f4add(Wa, f4sub(na, oa));
        }
    } else {
        #pragma unroll 4
        for (int k = 21; k <= 61; ++k) Wf = f4add(Wf, ld4(src, refl(i0 + k), l4));
        #pragma unroll 4
        for (int k = 22; k <= 62; ++k) Wa = f4add(Wa, ld4(src, refl(i0 - k), l4));

        #pragma unroll 4
        for (int i = i0; i <= i1; ++i) {
            float4 sm = f4scale(f4add(Wf, Wa), SC);
            float4 xv = ld4(src, i, l4);
            dst4[i * L4N + l4] = f4clip(xv, sm, clip);
            float4 nf = ld4(src, refl(i + 62), l4);
            float4 of = ld4(src, refl(i + 21), l4);
            float4 na = ld4(src, refl(i - 21), l4);
            float4 oa = ld4(src, refl(i - 62), l4);
            Wf = f4add(Wf, f4sub(nf, of));
            Wa = f4add(Wa, f4sub(na, oa));
        }
    }
}

// ---------------------------------------------------------------------------
// Stage 3 (w=25, gap=0) + final divide: out = x / box25(c2).
// grid = (L4N/THREADS, NTY). Fast path for tiles needing no reflection.
// ---------------------------------------------------------------------------
__global__ void stage3_kernel(const float* __restrict__ c2,
                              const float* __restrict__ x,
                              float* __restrict__ out)
{
    const int l4 = blockIdx.x * THREADS + threadIdx.x;
    const int t0 = blockIdx.y * TB;
    const int i1 = t0 + TB - 1;
    const float R25 = 1.0f / 25.0f;
    float4* __restrict__ out4 = reinterpret_cast<float4*>(out);

    float4 W = make_float4(0.f, 0.f, 0.f, 0.f);
    const bool fast = (t0 >= 13) && (i1 + 13 <= NB - 1);

    if (fast) {
        #pragma unroll
        for (int k = -12; k <= 12; ++k) W = f4add(W, ld4(c2, t0 + k, l4));

        #pragma unroll 8
        for (int i = t0; i <= i1; ++i) {
            float4 f  = f4scale(W, R25);
            float4 xv = ld4(x, i, l4);
            out4[i * L4N + l4] = make_float4(__fdiv_rn(xv.x, f.x),
                                             __fdiv_rn(xv.y, f.y),
                                             __fdiv_rn(xv.z, f.z),
                                             __fdiv_rn(xv.w, f.w));
            W = f4add(W, f4sub(ld4(c2, i + 13, l4), ld4(c2, i - 12, l4)));
        }
    } else {
        #pragma unroll
        for (int k = -12; k <= 12; ++k) W = f4add(W, ld4(c2, refl(t0 + k), l4));

        #pragma unroll 4
        for (int i = t0; i <= i1; ++i) {
            float4 f  = f4scale(W, R25);
            float4 xv = ld4(x, i, l4);
            out4[i * L4N + l4] = make_float4(__fdiv_rn(xv.x, f.x),
                                             __fdiv_rn(xv.y, f.y),
                                             __fdiv_rn(xv.z, f.z),
                                             __fdiv_rn(xv.w, f.w));
            W = f4add(W, f4sub(ld4(c2, refl(i + 13), l4),
                               ld4(c2, refl(i - 12), l4)));
        }
    }
}

// ---------------------------------------------------------------------------
extern "C" void kernel_launch(void* const* d_in, const int* in_sizes, int n_in,
                              void* d_out, int out_size)
{
    const float* x = (const float*)d_in[0];
    float* out     = (float*)d_out;

    float *c1 = nullptr, *c2 = nullptr;
    cudaGetSymbolAddress((void**)&c1, g_c1);
    cudaGetSymbolAddress((void**)&c2, g_c2);

    dim3 blk(THREADS);
    dim3 gStage(L4N / THREADS, NTY + 83);   // (4, 211): tiles + edge bins
    dim3 gS3(L4N / THREADS, NTY);           // (4, 128)

    stage_kernel<<<gStage, blk>>>(x,  c1, 3.0f);
    stage_kernel<<<gStage, blk>>>(c1, c2, 2.0f);
    stage3_kernel<<<gS3, blk>>>(c2, x, out);
}